// round 1
// baseline (speedup 1.0000x reference)
#include <cuda_runtime.h>
#include <cuda_bf16.h>
#include <math.h>

// ---------------------------------------------------------------------------
// Problem constants (fixed shapes from metadata)
// ---------------------------------------------------------------------------
#define BATCH   2
#define NPTS    8192           // N == M
#define CHUNKS  4
#define CHUNK_SZ (NPTS / CHUNKS)   // 2048
#define TILE    256

#define VD 64
#define VH 128
#define VW 128
#define VOL_PER_B (VD * VH * VW)       // 1048576
#define VOL_TOT   (BATCH * VOL_PER_B)  // 2097152

#define DH 512
#define DW 512
#define DPIX_PER_B (DH * DW)           // 262144
#define DPIX_TOT   (BATCH * DPIX_PER_B)

// ---------------------------------------------------------------------------
// Device scratch (static — no allocations allowed)
// ---------------------------------------------------------------------------
struct Acc {
    double chamfer_sum;
    double inter[2], psum[2], gsum[2];
    double g_sum[2], g2_sum[2];
    double gradx, grady, mask_num, mask_den;
};
__device__ Acc g_acc;

__device__ float g_minpart[CHUNKS * 2 * BATCH * NPTS];   // [chunk][dir][b][pt]

__device__ float g_sp1[VOL_TOT];   // eroded-W pred
__device__ float g_sg1[VOL_TOT];   // eroded-W gt
__device__ float g_sp2[VOL_TOT];   // eroded-WH pred
__device__ float g_sg2[VOL_TOT];   // eroded-WH gt

// ---------------------------------------------------------------------------
// Utilities
// ---------------------------------------------------------------------------
__device__ __forceinline__ float warpReduceSum(float v) {
    #pragma unroll
    for (int o = 16; o > 0; o >>= 1)
        v += __shfl_down_sync(0xffffffffu, v, o);
    return v;
}

// Valid result only in thread 0. Safe to call repeatedly (internal syncs).
__device__ __forceinline__ float blockReduceSum(float v) {
    __shared__ float sbuf[32];
    int lane = threadIdx.x & 31;
    int wid  = threadIdx.x >> 5;
    v = warpReduceSum(v);
    __syncthreads();
    if (lane == 0) sbuf[wid] = v;
    __syncthreads();
    if (wid == 0) {
        int nw = (blockDim.x + 31) >> 5;
        v = (lane < nw) ? sbuf[lane] : 0.f;
        v = warpReduceSum(v);
    }
    return v;
}

// ---------------------------------------------------------------------------
// Init: zero accumulators
// ---------------------------------------------------------------------------
__global__ void init_kernel() {
    double* a = (double*)&g_acc;
    const int n = sizeof(Acc) / sizeof(double);
    if (threadIdx.x < n) a[threadIdx.x] = 0.0;
}

// ---------------------------------------------------------------------------
// Chamfer: partial mins.  grid(NPTS/256, CHUNKS, BATCH*2), block 256
// d'(p,g) = |g|^2 - 2 p.g   (add |p|^2 later)
// ---------------------------------------------------------------------------
__global__ __launch_bounds__(256) void chamfer_kernel(const float* __restrict__ pred,
                                                      const float* __restrict__ gt) {
    const int tid   = threadIdx.x;
    const int pt    = blockIdx.x * 256 + tid;
    const int chunk = blockIdx.y;
    const int bz    = blockIdx.z;
    const int b     = bz & 1;
    const int dir   = bz >> 1;

    const float* Q = (dir ? gt : pred) + (size_t)b * NPTS * 3;
    const float* T = (dir ? pred : gt) + (size_t)b * NPTS * 3;

    const float qx = Q[pt * 3 + 0];
    const float qy = Q[pt * 3 + 1];
    const float qz = Q[pt * 3 + 2];

    __shared__ float4 tile[TILE];

    float m0 = INFINITY, m1 = INFINITY, m2 = INFINITY, m3 = INFINITY;
    const int base = chunk * CHUNK_SZ;

    for (int t0 = 0; t0 < CHUNK_SZ; t0 += TILE) {
        int j = base + t0 + tid;
        float gx = T[j * 3 + 0];
        float gy = T[j * 3 + 1];
        float gz = T[j * 3 + 2];
        __syncthreads();   // previous tile fully consumed
        tile[tid] = make_float4(-2.f * gx, -2.f * gy, -2.f * gz,
                                fmaf(gx, gx, fmaf(gy, gy, gz * gz)));
        __syncthreads();
        #pragma unroll 8
        for (int k = 0; k < TILE; k += 4) {
            float4 a = tile[k + 0];
            float4 bb = tile[k + 1];
            float4 c = tile[k + 2];
            float4 d = tile[k + 3];
            float d0 = fmaf(qx, a.x,  fmaf(qy, a.y,  fmaf(qz, a.z,  a.w)));
            float d1 = fmaf(qx, bb.x, fmaf(qy, bb.y, fmaf(qz, bb.z, bb.w)));
            float d2 = fmaf(qx, c.x,  fmaf(qy, c.y,  fmaf(qz, c.z,  c.w)));
            float d3 = fmaf(qx, d.x,  fmaf(qy, d.y,  fmaf(qz, d.z,  d.w)));
            m0 = fminf(m0, d0);
            m1 = fminf(m1, d1);
            m2 = fminf(m2, d2);
            m3 = fminf(m3, d3);
        }
    }
    float m = fminf(fminf(m0, m1), fminf(m2, m3));
    g_minpart[((chunk * 2 + dir) * 2 + b) * NPTS + pt] = m;
}

// ---------------------------------------------------------------------------
// Chamfer reduce: min over chunks, add |q|^2, sum.  <<<128,256>>>
// ---------------------------------------------------------------------------
__global__ __launch_bounds__(256) void chamfer_reduce_kernel(const float* __restrict__ pred,
                                                             const float* __restrict__ gt) {
    const int idx = blockIdx.x * 256 + threadIdx.x;   // 0..32767
    const int pt  = idx & (NPTS - 1);
    const int b   = (idx >> 13) & 1;
    const int dir = idx >> 14;

    const float* Q = (dir ? gt : pred) + (size_t)b * NPTS * 3 + (size_t)pt * 3;
    const float q2 = fmaf(Q[0], Q[0], fmaf(Q[1], Q[1], Q[2] * Q[2]));

    float m = INFINITY;
    #pragma unroll
    for (int c = 0; c < CHUNKS; c++)
        m = fminf(m, g_minpart[((c * 2 + dir) * 2 + b) * NPTS + pt]);

    float v = m + q2;
    float s = blockReduceSum(v);
    if (threadIdx.x == 0) atomicAdd(&g_acc.chamfer_sum, (double)s);
}

// ---------------------------------------------------------------------------
// clDice: separable 3x3x3 min-pool (SAME, OOB ignored).
// sigmoid is monotonic => erode raw pred, sigmoid at the end.
// ---------------------------------------------------------------------------
__global__ __launch_bounds__(256) void erode_w_kernel(const float* __restrict__ pv,
                                                      const float* __restrict__ gv) {
    const int i = blockIdx.x * 256 + threadIdx.x;   // < VOL_TOT
    const int w = i & (VW - 1);
    float p = pv[i], g = gv[i];
    if (w > 0)      { p = fminf(p, pv[i - 1]); g = fminf(g, gv[i - 1]); }
    if (w < VW - 1) { p = fminf(p, pv[i + 1]); g = fminf(g, gv[i + 1]); }
    g_sp1[i] = p;
    g_sg1[i] = g;
}

__global__ __launch_bounds__(256) void erode_h_kernel() {
    const int i = blockIdx.x * 256 + threadIdx.x;
    const int h = (i >> 7) & (VH - 1);
    float p = g_sp1[i], g = g_sg1[i];
    if (h > 0)      { p = fminf(p, g_sp1[i - VW]); g = fminf(g, g_sg1[i - VW]); }
    if (h < VH - 1) { p = fminf(p, g_sp1[i + VW]); g = fminf(g, g_sg1[i + VW]); }
    g_sp2[i] = p;
    g_sg2[i] = g;
}

// min along D + sigmoid + per-batch reduction.  blocks of 1024 elements.
__global__ __launch_bounds__(256) void erode_d_reduce_kernel() {
    const int base = blockIdx.x * 1024;
    const int b    = base >> 20;   // VOL_PER_B = 2^20
    float s_i = 0.f, s_p = 0.f, s_g = 0.f;
    #pragma unroll
    for (int t = 0; t < 4; t++) {
        const int i = base + t * 256 + threadIdx.x;
        const int d = (i >> 14) & (VD - 1);
        float p = g_sp2[i], g = g_sg2[i];
        if (d > 0)      { p = fminf(p, g_sp2[i - VH * VW]); g = fminf(g, g_sg2[i - VH * VW]); }
        if (d < VD - 1) { p = fminf(p, g_sp2[i + VH * VW]); g = fminf(g, g_sg2[i + VH * VW]); }
        p = 1.f / (1.f + expf(-p));
        s_i = fmaf(p, g, s_i);
        s_p += p;
        s_g += g;
    }
    float r;
    r = blockReduceSum(s_i); if (threadIdx.x == 0) atomicAdd(&g_acc.inter[b], (double)r);
    r = blockReduceSum(s_p); if (threadIdx.x == 0) atomicAdd(&g_acc.psum[b], (double)r);
    r = blockReduceSum(s_g); if (threadIdx.x == 0) atomicAdd(&g_acc.gsum[b], (double)r);
}

// ---------------------------------------------------------------------------
// Depth loss: fused SILog + gradient L1 + masked L1.  blocks of 1024 elements.
// ---------------------------------------------------------------------------
__global__ __launch_bounds__(256) void depth_kernel(const float* __restrict__ pred,
                                                    const float* __restrict__ gt,
                                                    const float* __restrict__ mask) {
    const int base = blockIdx.x * 1024;
    const int b    = base >> 18;   // DPIX_PER_B = 2^18
    float s_g = 0.f, s_g2 = 0.f, s_gx = 0.f, s_gy = 0.f, s_mn = 0.f, s_md = 0.f;
    #pragma unroll
    for (int t = 0; t < 4; t++) {
        const int i = base + t * 256 + threadIdx.x;
        const int w = i & (DW - 1);
        const int h = (i >> 9) & (DH - 1);
        const float p = pred[i];
        const float g = gt[i];
        const float lg = logf(p + 0.1f) - logf(g + 0.1f);
        s_g  += lg;
        s_g2  = fmaf(lg, lg, s_g2);
        if (h < DH - 1) {
            float pg = fabsf(p - pred[i + DW]);
            float gg = fabsf(g - gt[i + DW]);
            s_gx += fabsf(pg - gg);
        }
        if (w < DW - 1) {
            float pg = fabsf(p - pred[i + 1]);
            float gg = fabsf(g - gt[i + 1]);
            s_gy += fabsf(pg - gg);
        }
        const float mk = mask[i];
        s_mn = fmaf(fabsf(p - g), mk, s_mn);
        s_md += mk;
    }
    float r;
    r = blockReduceSum(s_g);  if (threadIdx.x == 0) atomicAdd(&g_acc.g_sum[b],  (double)r);
    r = blockReduceSum(s_g2); if (threadIdx.x == 0) atomicAdd(&g_acc.g2_sum[b], (double)r);
    r = blockReduceSum(s_gx); if (threadIdx.x == 0) atomicAdd(&g_acc.gradx,    (double)r);
    r = blockReduceSum(s_gy); if (threadIdx.x == 0) atomicAdd(&g_acc.grady,    (double)r);
    r = blockReduceSum(s_mn); if (threadIdx.x == 0) atomicAdd(&g_acc.mask_num, (double)r);
    r = blockReduceSum(s_md); if (threadIdx.x == 0) atomicAdd(&g_acc.mask_den, (double)r);
}

// ---------------------------------------------------------------------------
// Finalize
// ---------------------------------------------------------------------------
__global__ void finalize_kernel(const int* __restrict__ iter_ptr,
                                float* __restrict__ out) {
    if (threadIdx.x != 0 || blockIdx.x != 0) return;
    const Acc& a = g_acc;

    // chamfer: mean over [B,N] + mean over [B,M], both divide by B*8192
    double chamfer = a.chamfer_sum / (double)(BATCH * NPTS);

    // clDice
    const double smooth = 1e-5;
    double dice0 = (2.0 * a.inter[0] + smooth) / (a.psum[0] + a.gsum[0] + smooth);
    double dice1 = (2.0 * a.inter[1] + smooth) / (a.psum[1] + a.gsum[1] + smooth);
    double cldice = 1.0 - 0.5 * (dice0 + dice1);

    // depth
    const double Np = (double)DPIX_PER_B;
    double m0 = a.g_sum[0] / Np, m1 = a.g_sum[1] / Np;
    double v0 = a.g2_sum[0] / Np - m0 * m0;
    double v1 = a.g2_sum[1] / Np - m1 * m1;
    double silog = 10.0 * 0.5 * (v0 + v1) + 10.0 * 0.5 * (m0 * m0 + m1 * m1);
    double grad = a.gradx / (double)(BATCH * (DH - 1) * DW)
                + a.grady / (double)(BATCH * DH * (DW - 1));
    double mask_l1 = a.mask_num / (a.mask_den + 1e-8);
    double dloss = silog + grad + mask_l1;

    int it = *iter_ptr;
    if (it < 1) it = 1;
    double gamma1 = 2.0 * log((double)it / 20000.0);

    out[0] = (float)(gamma1 * chamfer + 0.5 * cldice + 0.01 * dloss);
}

// ---------------------------------------------------------------------------
// Launch
// ---------------------------------------------------------------------------
extern "C" void kernel_launch(void* const* d_in, const int* in_sizes, int n_in,
                              void* d_out, int out_size) {
    const float* pred_centers = (const float*)d_in[0];
    const float* pred_volume  = (const float*)d_in[1];
    const float* pred_depth   = (const float*)d_in[2];
    const float* gt_points    = (const float*)d_in[3];
    const float* gt_volume    = (const float*)d_in[4];
    const float* gt_depth     = (const float*)d_in[5];
    const float* depth_mask   = (const float*)d_in[6];
    const int*   iteration    = (const int*)d_in[7];
    float* out = (float*)d_out;

    init_kernel<<<1, 32>>>();

    dim3 cgrid(NPTS / 256, CHUNKS, BATCH * 2);
    chamfer_kernel<<<cgrid, 256>>>(pred_centers, gt_points);
    chamfer_reduce_kernel<<<(2 * BATCH * NPTS) / 256, 256>>>(pred_centers, gt_points);

    erode_w_kernel<<<VOL_TOT / 256, 256>>>(pred_volume, gt_volume);
    erode_h_kernel<<<VOL_TOT / 256, 256>>>();
    erode_d_reduce_kernel<<<VOL_TOT / 1024, 256>>>();

    depth_kernel<<<DPIX_TOT / 1024, 256>>>(pred_depth, gt_depth, depth_mask);

    finalize_kernel<<<1, 32>>>(iteration, out);
}

// round 2
// speedup vs baseline: 1.4440x; 1.4440x over previous
#include <cuda_runtime.h>
#include <cuda_bf16.h>
#include <math.h>

// ---------------------------------------------------------------------------
// Problem constants (fixed shapes from metadata)
// ---------------------------------------------------------------------------
#define BATCH   2
#define NPTS    8192           // N == M
#define CHUNKS  4
#define CHUNK_SZ (NPTS / CHUNKS)   // 2048
#define TILE    256
#define QBLK    2                  // queries per thread

#define VD 64
#define VH 128
#define VW 128
#define VOL_PER_B (VD * VH * VW)       // 1048576
#define VOL_TOT   (BATCH * VOL_PER_B)  // 2097152
#define DCHUNK 16

#define DH 512
#define DW 512
#define DPIX_PER_B (DH * DW)           // 262144
#define DPIX_TOT   (BATCH * DPIX_PER_B)

// ---------------------------------------------------------------------------
// Device scratch (static — no allocations allowed)
// ---------------------------------------------------------------------------
struct Acc {
    double chamfer_sum;
    double inter[2], psum[2], gsum[2];
    double g_sum[2], g2_sum[2];
    double gradx, grady, mask_num, mask_den;
};
__device__ Acc g_acc;

__device__ float g_minpart[CHUNKS * 2 * BATCH * NPTS];   // [chunk][dir][b][pt]

// ---------------------------------------------------------------------------
// f32x2 packed helpers (sm_103a; ptxas will not auto-fuse — must be PTX)
// ---------------------------------------------------------------------------
__device__ __forceinline__ unsigned long long fma2(unsigned long long a,
                                                   unsigned long long b,
                                                   unsigned long long c) {
    unsigned long long d;
    asm("fma.rn.f32x2 %0, %1, %2, %3;" : "=l"(d) : "l"(a), "l"(b), "l"(c));
    return d;
}
__device__ __forceinline__ unsigned long long pack2(float a, float b) {
    unsigned long long r;
    asm("mov.b64 %0, {%1, %2};" : "=l"(r) : "f"(a), "f"(b));
    return r;
}
__device__ __forceinline__ void unpack2(unsigned long long v, float& a, float& b) {
    asm("mov.b64 {%0, %1}, %2;" : "=f"(a), "=f"(b) : "l"(v));
}

// ---------------------------------------------------------------------------
// Reductions
// ---------------------------------------------------------------------------
__device__ __forceinline__ float warpReduceSum(float v) {
    #pragma unroll
    for (int o = 16; o > 0; o >>= 1)
        v += __shfl_down_sync(0xffffffffu, v, o);
    return v;
}

// Valid result only in thread 0. Safe to call repeatedly (internal syncs).
__device__ __forceinline__ float blockReduceSum(float v) {
    __shared__ float sbuf[32];
    int lane = threadIdx.x & 31;
    int wid  = threadIdx.x >> 5;
    v = warpReduceSum(v);
    __syncthreads();
    if (lane == 0) sbuf[wid] = v;
    __syncthreads();
    if (wid == 0) {
        int nw = (blockDim.x + 31) >> 5;
        v = (lane < nw) ? sbuf[lane] : 0.f;
        v = warpReduceSum(v);
    }
    return v;
}

// ---------------------------------------------------------------------------
// Init: zero accumulators
// ---------------------------------------------------------------------------
__global__ void init_kernel() {
    double* a = (double*)&g_acc;
    const int n = sizeof(Acc) / sizeof(double);
    if (threadIdx.x < n) a[threadIdx.x] = 0.0;
}

// ---------------------------------------------------------------------------
// Chamfer partial mins, packed f32x2, 2 queries / thread.
// grid (NPTS/(256*QBLK)=16, CHUNKS, BATCH*2), block 256
// d'(q,g) = |g|^2 - 2 q.g   (|q|^2 added in the reduce kernel)
// Tile layout (per candidate pair k):
//   s_xy[k].x = (-2x_{2k}, -2x_{2k+1})   s_xy[k].y = (-2y_{2k}, -2y_{2k+1})
//   s_zw[k].x = (-2z_{2k}, -2z_{2k+1})   s_zw[k].y = (|g|^2_{2k}, |g|^2_{2k+1})
// ---------------------------------------------------------------------------
__global__ __launch_bounds__(256) void chamfer_kernel(const float* __restrict__ pred,
                                                      const float* __restrict__ gt) {
    const int tid   = threadIdx.x;
    const int pt0   = blockIdx.x * (256 * QBLK) + tid;
    const int pt1   = pt0 + 256;
    const int chunk = blockIdx.y;
    const int bz    = blockIdx.z;
    const int b     = bz & 1;
    const int dir   = bz >> 1;

    const float* Q = (dir ? gt : pred) + (size_t)b * NPTS * 3;
    const float* T = (dir ? pred : gt) + (size_t)b * NPTS * 3;

    const float q0x = Q[pt0 * 3 + 0], q0y = Q[pt0 * 3 + 1], q0z = Q[pt0 * 3 + 2];
    const float q1x = Q[pt1 * 3 + 0], q1y = Q[pt1 * 3 + 1], q1z = Q[pt1 * 3 + 2];
    const unsigned long long q0x2 = pack2(q0x, q0x), q0y2 = pack2(q0y, q0y), q0z2 = pack2(q0z, q0z);
    const unsigned long long q1x2 = pack2(q1x, q1x), q1y2 = pack2(q1y, q1y), q1z2 = pack2(q1z, q1z);

    __shared__ ulonglong2 s_xy[TILE / 2];
    __shared__ ulonglong2 s_zw[TILE / 2];

    float m00 = INFINITY, m01 = INFINITY, m10 = INFINITY, m11 = INFINITY;
    const int base = chunk * CHUNK_SZ;

    for (int t0 = 0; t0 < CHUNK_SZ; t0 += TILE) {
        const int j = base + t0 + tid;
        const float gx = T[j * 3 + 0];
        const float gy = T[j * 3 + 1];
        const float gz = T[j * 3 + 2];
        __syncthreads();   // previous tile fully consumed
        {
            float* fxy = (float*)s_xy;
            float* fzw = (float*)s_zw;
            const int k4 = (tid >> 1) * 4 + (tid & 1);
            fxy[k4]     = -2.f * gx;
            fxy[k4 + 2] = -2.f * gy;
            fzw[k4]     = -2.f * gz;
            fzw[k4 + 2] = fmaf(gx, gx, fmaf(gy, gy, gz * gz));
        }
        __syncthreads();
        #pragma unroll 8
        for (int k = 0; k < TILE / 2; k++) {
            const ulonglong2 xy = s_xy[k];
            const ulonglong2 zw = s_zw[k];
            unsigned long long a0 = fma2(q0x2, xy.x, zw.y);
            a0 = fma2(q0y2, xy.y, a0);
            a0 = fma2(q0z2, zw.x, a0);
            unsigned long long a1 = fma2(q1x2, xy.x, zw.y);
            a1 = fma2(q1y2, xy.y, a1);
            a1 = fma2(q1z2, zw.x, a1);
            float lo, hi;
            unpack2(a0, lo, hi);
            m00 = fminf(m00, lo); m01 = fminf(m01, hi);
            unpack2(a1, lo, hi);
            m10 = fminf(m10, lo); m11 = fminf(m11, hi);
        }
    }
    const int slot = ((chunk * 2 + dir) * 2 + b) * NPTS;
    g_minpart[slot + pt0] = fminf(m00, m01);
    g_minpart[slot + pt1] = fminf(m10, m11);
}

// ---------------------------------------------------------------------------
// Chamfer reduce: min over chunks, add |q|^2, sum.  <<<128,256>>>
// ---------------------------------------------------------------------------
__global__ __launch_bounds__(256) void chamfer_reduce_kernel(const float* __restrict__ pred,
                                                             const float* __restrict__ gt) {
    const int idx = blockIdx.x * 256 + threadIdx.x;   // 0..32767
    const int pt  = idx & (NPTS - 1);
    const int b   = (idx >> 13) & 1;
    const int dir = idx >> 14;

    const float* Q = (dir ? gt : pred) + (size_t)b * NPTS * 3 + (size_t)pt * 3;
    const float q2 = fmaf(Q[0], Q[0], fmaf(Q[1], Q[1], Q[2] * Q[2]));

    float m = INFINITY;
    #pragma unroll
    for (int c = 0; c < CHUNKS; c++)
        m = fminf(m, g_minpart[((c * 2 + dir) * 2 + b) * NPTS + pt]);

    float s = blockReduceSum(m + q2);
    if (threadIdx.x == 0) atomicAdd(&g_acc.chamfer_sum, (double)s);
}

// ---------------------------------------------------------------------------
// clDice fully fused: separable 3x3x3 min-pool (SAME, OOB ignored) + sigmoid
// + reduction, single pass, no intermediates.
//   h-min: 3 predicated global rows (L2-reused by neighboring blocks)
//   w-min: smem row exchange with +inf halo
//   d-min: rolling 3-register window
// sigmoid is monotonic => erode raw pred logits, sigmoid at the end.
// grid (VH, VD/DCHUNK, BATCH), block VW=128
// ---------------------------------------------------------------------------
__global__ __launch_bounds__(128) void cldice_kernel(const float* __restrict__ pv,
                                                     const float* __restrict__ gv) {
    const int w  = threadIdx.x;
    const int h  = blockIdx.x;
    const int d0 = blockIdx.y * DCHUNK;
    const int b  = blockIdx.z;
    const float* P = pv + (size_t)b * VOL_PER_B;
    const float* G = gv + (size_t)b * VOL_PER_B;
    const bool hm = (h > 0), hp = (h < VH - 1);

    __shared__ float sp[VW + 2], sg[VW + 2];
    if (w == 0) { sp[0] = INFINITY; sp[VW + 1] = INFINITY; sg[0] = INFINITY; sg[VW + 1] = INFINITY; }

    float wa = INFINITY, wb = INFINITY;   // pred d-window
    float va = INFINITY, vb = INFINITY;   // gt   d-window
    float accI = 0.f, accP = 0.f, accG = 0.f;

    for (int dd = d0 - 1; dd <= d0 + DCHUNK; dd++) {
        float ph = INFINITY, gh = INFINITY;
        if (dd >= 0 && dd < VD) {
            const int rb = dd * VH * VW + h * VW + w;
            ph = P[rb]; gh = G[rb];
            if (hm) { ph = fminf(ph, P[rb - VW]); gh = fminf(gh, G[rb - VW]); }
            if (hp) { ph = fminf(ph, P[rb + VW]); gh = fminf(gh, G[rb + VW]); }
        }
        __syncthreads();                 // prior iteration's smem reads done
        sp[w + 1] = ph; sg[w + 1] = gh;
        __syncthreads();
        const float pc = fminf(fminf(sp[w], ph), sp[w + 2]);
        const float gc = fminf(fminf(sg[w], gh), sg[w + 2]);
        if (dd > d0) {                   // emit dout = dd-1 in [d0, d0+DCHUNK)
            const float pe = fminf(fminf(wa, wb), pc);
            const float ge = fminf(fminf(va, vb), gc);
            const float s = 1.f / (1.f + __expf(-pe));
            accI = fmaf(s, ge, accI);
            accP += s;
            accG += ge;
        }
        wa = wb; wb = pc;
        va = vb; vb = gc;
    }

    float r;
    r = blockReduceSum(accI); if (threadIdx.x == 0) atomicAdd(&g_acc.inter[b], (double)r);
    r = blockReduceSum(accP); if (threadIdx.x == 0) atomicAdd(&g_acc.psum[b], (double)r);
    r = blockReduceSum(accG); if (threadIdx.x == 0) atomicAdd(&g_acc.gsum[b], (double)r);
}

// ---------------------------------------------------------------------------
// Depth loss, float4-vectorized: SILog + gradient L1 + masked L1.
// grid DPIX_TOT/1024 = 512 blocks, 256 threads, 4 px/thread (one row segment).
// ---------------------------------------------------------------------------
__global__ __launch_bounds__(256) void depth_kernel(const float* __restrict__ pred,
                                                    const float* __restrict__ gt,
                                                    const float* __restrict__ mask) {
    const int vi = blockIdx.x * 256 + threadIdx.x;    // float4 index
    const int i  = vi * 4;
    const int b  = i >> 18;                           // DPIX_PER_B = 2^18
    const int w0 = i & (DW - 1);
    const int h  = (i >> 9) & (DH - 1);

    const float4 p = ((const float4*)pred)[vi];
    const float4 g = ((const float4*)gt)[vi];
    const float4 mk = ((const float4*)mask)[vi];

    // SILog terms
    float lg0 = __logf(p.x + 0.1f) - __logf(g.x + 0.1f);
    float lg1 = __logf(p.y + 0.1f) - __logf(g.y + 0.1f);
    float lg2 = __logf(p.z + 0.1f) - __logf(g.z + 0.1f);
    float lg3 = __logf(p.w + 0.1f) - __logf(g.w + 0.1f);
    float s_g  = lg0 + lg1 + lg2 + lg3;
    float s_g2 = fmaf(lg0, lg0, fmaf(lg1, lg1, fmaf(lg2, lg2, lg3 * lg3)));

    // gradient along h (x in reference)
    float s_gx = 0.f;
    if (h < DH - 1) {
        const float4 pd = ((const float4*)pred)[vi + DW / 4];
        const float4 gd = ((const float4*)gt)[vi + DW / 4];
        s_gx += fabsf(fabsf(p.x - pd.x) - fabsf(g.x - gd.x));
        s_gx += fabsf(fabsf(p.y - pd.y) - fabsf(g.y - gd.y));
        s_gx += fabsf(fabsf(p.z - pd.z) - fabsf(g.z - gd.z));
        s_gx += fabsf(fabsf(p.w - pd.w) - fabsf(g.w - gd.w));
    }
    // gradient along w (y in reference)
    float s_gy = 0.f;
    s_gy += fabsf(fabsf(p.x - p.y) - fabsf(g.x - g.y));
    s_gy += fabsf(fabsf(p.y - p.z) - fabsf(g.y - g.z));
    s_gy += fabsf(fabsf(p.z - p.w) - fabsf(g.z - g.w));
    if (w0 + 4 < DW) {
        const float pn = pred[i + 4];
        const float gn = gt[i + 4];
        s_gy += fabsf(fabsf(p.w - pn) - fabsf(g.w - gn));
    }
    // masked L1
    float s_mn = fabsf(p.x - g.x) * mk.x + fabsf(p.y - g.y) * mk.y
               + fabsf(p.z - g.z) * mk.z + fabsf(p.w - g.w) * mk.w;
    float s_md = mk.x + mk.y + mk.z + mk.w;

    float r;
    r = blockReduceSum(s_g);  if (threadIdx.x == 0) atomicAdd(&g_acc.g_sum[b],  (double)r);
    r = blockReduceSum(s_g2); if (threadIdx.x == 0) atomicAdd(&g_acc.g2_sum[b], (double)r);
    r = blockReduceSum(s_gx); if (threadIdx.x == 0) atomicAdd(&g_acc.gradx,    (double)r);
    r = blockReduceSum(s_gy); if (threadIdx.x == 0) atomicAdd(&g_acc.grady,    (double)r);
    r = blockReduceSum(s_mn); if (threadIdx.x == 0) atomicAdd(&g_acc.mask_num, (double)r);
    r = blockReduceSum(s_md); if (threadIdx.x == 0) atomicAdd(&g_acc.mask_den, (double)r);
}

// ---------------------------------------------------------------------------
// Finalize
// ---------------------------------------------------------------------------
__global__ void finalize_kernel(const int* __restrict__ iter_ptr,
                                float* __restrict__ out) {
    if (threadIdx.x != 0 || blockIdx.x != 0) return;
    const Acc& a = g_acc;

    double chamfer = a.chamfer_sum / (double)(BATCH * NPTS);

    const double smooth = 1e-5;
    double dice0 = (2.0 * a.inter[0] + smooth) / (a.psum[0] + a.gsum[0] + smooth);
    double dice1 = (2.0 * a.inter[1] + smooth) / (a.psum[1] + a.gsum[1] + smooth);
    double cldice = 1.0 - 0.5 * (dice0 + dice1);

    const double Np = (double)DPIX_PER_B;
    double m0 = a.g_sum[0] / Np, m1 = a.g_sum[1] / Np;
    double v0 = a.g2_sum[0] / Np - m0 * m0;
    double v1 = a.g2_sum[1] / Np - m1 * m1;
    double silog = 10.0 * 0.5 * (v0 + v1) + 10.0 * 0.5 * (m0 * m0 + m1 * m1);
    double grad = a.gradx / (double)(BATCH * (DH - 1) * DW)
                + a.grady / (double)(BATCH * DH * (DW - 1));
    double mask_l1 = a.mask_num / (a.mask_den + 1e-8);
    double dloss = silog + grad + mask_l1;

    int it = *iter_ptr;
    if (it < 1) it = 1;
    double gamma1 = 2.0 * log((double)it / 20000.0);

    out[0] = (float)(gamma1 * chamfer + 0.5 * cldice + 0.01 * dloss);
}

// ---------------------------------------------------------------------------
// Launch
// ---------------------------------------------------------------------------
extern "C" void kernel_launch(void* const* d_in, const int* in_sizes, int n_in,
                              void* d_out, int out_size) {
    const float* pred_centers = (const float*)d_in[0];
    const float* pred_volume  = (const float*)d_in[1];
    const float* pred_depth   = (const float*)d_in[2];
    const float* gt_points    = (const float*)d_in[3];
    const float* gt_volume    = (const float*)d_in[4];
    const float* gt_depth     = (const float*)d_in[5];
    const float* depth_mask   = (const float*)d_in[6];
    const int*   iteration    = (const int*)d_in[7];
    float* out = (float*)d_out;

    init_kernel<<<1, 32>>>();

    dim3 cgrid(NPTS / (256 * QBLK), CHUNKS, BATCH * 2);
    chamfer_kernel<<<cgrid, 256>>>(pred_centers, gt_points);
    chamfer_reduce_kernel<<<(2 * BATCH * NPTS) / 256, 256>>>(pred_centers, gt_points);

    dim3 vgrid(VH, VD / DCHUNK, BATCH);
    cldice_kernel<<<vgrid, 128>>>(pred_volume, gt_volume);

    depth_kernel<<<DPIX_TOT / 1024, 256>>>(pred_depth, gt_depth, depth_mask);

    finalize_kernel<<<1, 32>>>(iteration, out);
}

// round 3
// speedup vs baseline: 1.7999x; 1.2464x over previous
#include <cuda_runtime.h>
#include <cuda_bf16.h>
#include <math.h>

// ---------------------------------------------------------------------------
// Problem constants (fixed shapes from metadata)
// ---------------------------------------------------------------------------
#define BATCH   2
#define NPTS    8192           // N == M
#define CHUNKS  16
#define CHUNK_SZ (NPTS / CHUNKS)   // 512
#define TILE    256
#define QBLK    2                  // queries per thread

#define VD 64
#define VH 128
#define VW 128
#define VOL_PER_B (VD * VH * VW)       // 1048576
#define DCHUNK 4

#define DH 512
#define DW 512
#define DPIX_PER_B (DH * DW)           // 262144
#define DPIX_TOT   (BATCH * DPIX_PER_B)

// ---------------------------------------------------------------------------
// Device scratch (static — no allocations allowed)
// ---------------------------------------------------------------------------
struct Acc {
    double chamfer_sum;
    double inter[2], psum[2], gsum[2];
    double g_sum[2], g2_sum[2];
    double gradx, grady, mask_num, mask_den;
};
__device__ Acc g_acc;

__device__ float g_minpart[CHUNKS * 2 * BATCH * NPTS];   // [chunk][dir][b][pt]

// ---------------------------------------------------------------------------
// f32x2 packed helpers (sm_103a; ptxas will not auto-fuse — must be PTX)
// ---------------------------------------------------------------------------
__device__ __forceinline__ unsigned long long fma2(unsigned long long a,
                                                   unsigned long long b,
                                                   unsigned long long c) {
    unsigned long long d;
    asm("fma.rn.f32x2 %0, %1, %2, %3;" : "=l"(d) : "l"(a), "l"(b), "l"(c));
    return d;
}
__device__ __forceinline__ unsigned long long pack2(float a, float b) {
    unsigned long long r;
    asm("mov.b64 %0, {%1, %2};" : "=l"(r) : "f"(a), "f"(b));
    return r;
}
__device__ __forceinline__ void unpack2(unsigned long long v, float& a, float& b) {
    asm("mov.b64 {%0, %1}, %2;" : "=f"(a), "=f"(b) : "l"(v));
}

// ---------------------------------------------------------------------------
// Reductions
// ---------------------------------------------------------------------------
__device__ __forceinline__ float warpReduceSum(float v) {
    #pragma unroll
    for (int o = 16; o > 0; o >>= 1)
        v += __shfl_down_sync(0xffffffffu, v, o);
    return v;
}

// Valid result only in thread 0. Safe to call repeatedly (internal syncs).
__device__ __forceinline__ float blockReduceSum(float v) {
    __shared__ float sbuf[32];
    int lane = threadIdx.x & 31;
    int wid  = threadIdx.x >> 5;
    v = warpReduceSum(v);
    __syncthreads();
    if (lane == 0) sbuf[wid] = v;
    __syncthreads();
    if (wid == 0) {
        int nw = (blockDim.x + 31) >> 5;
        v = (lane < nw) ? sbuf[lane] : 0.f;
        v = warpReduceSum(v);
    }
    return v;
}

// ---------------------------------------------------------------------------
// Init: zero accumulators
// ---------------------------------------------------------------------------
__global__ void init_kernel() {
    double* a = (double*)&g_acc;
    const int n = sizeof(Acc) / sizeof(double);
    if (threadIdx.x < n) a[threadIdx.x] = 0.0;
}

// ---------------------------------------------------------------------------
// Chamfer partial mins, packed f32x2, 2 queries / thread.
// grid (NPTS/(256*QBLK)=16, CHUNKS, BATCH*2), block 256
// d'(q,g) = |g|^2 - 2 q.g   (|q|^2 added in the reduce kernel)
// ---------------------------------------------------------------------------
__global__ __launch_bounds__(256) void chamfer_kernel(const float* __restrict__ pred,
                                                      const float* __restrict__ gt) {
    const int tid   = threadIdx.x;
    const int pt0   = blockIdx.x * (256 * QBLK) + tid;
    const int pt1   = pt0 + 256;
    const int chunk = blockIdx.y;
    const int bz    = blockIdx.z;
    const int b     = bz & 1;
    const int dir   = bz >> 1;

    const float* Q = (dir ? gt : pred) + (size_t)b * NPTS * 3;
    const float* T = (dir ? pred : gt) + (size_t)b * NPTS * 3;

    const float q0x = Q[pt0 * 3 + 0], q0y = Q[pt0 * 3 + 1], q0z = Q[pt0 * 3 + 2];
    const float q1x = Q[pt1 * 3 + 0], q1y = Q[pt1 * 3 + 1], q1z = Q[pt1 * 3 + 2];
    const unsigned long long q0x2 = pack2(q0x, q0x), q0y2 = pack2(q0y, q0y), q0z2 = pack2(q0z, q0z);
    const unsigned long long q1x2 = pack2(q1x, q1x), q1y2 = pack2(q1y, q1y), q1z2 = pack2(q1z, q1z);

    __shared__ ulonglong2 s_xy[TILE / 2];
    __shared__ ulonglong2 s_zw[TILE / 2];

    float m00 = INFINITY, m01 = INFINITY, m10 = INFINITY, m11 = INFINITY;
    const int base = chunk * CHUNK_SZ;

    for (int t0 = 0; t0 < CHUNK_SZ; t0 += TILE) {
        const int j = base + t0 + tid;
        const float gx = T[j * 3 + 0];
        const float gy = T[j * 3 + 1];
        const float gz = T[j * 3 + 2];
        __syncthreads();   // previous tile fully consumed
        {
            float* fxy = (float*)s_xy;
            float* fzw = (float*)s_zw;
            const int k4 = (tid >> 1) * 4 + (tid & 1);
            fxy[k4]     = -2.f * gx;
            fxy[k4 + 2] = -2.f * gy;
            fzw[k4]     = -2.f * gz;
            fzw[k4 + 2] = fmaf(gx, gx, fmaf(gy, gy, gz * gz));
        }
        __syncthreads();
        #pragma unroll 8
        for (int k = 0; k < TILE / 2; k++) {
            const ulonglong2 xy = s_xy[k];
            const ulonglong2 zw = s_zw[k];
            unsigned long long a0 = fma2(q0x2, xy.x, zw.y);
            a0 = fma2(q0y2, xy.y, a0);
            a0 = fma2(q0z2, zw.x, a0);
            unsigned long long a1 = fma2(q1x2, xy.x, zw.y);
            a1 = fma2(q1y2, xy.y, a1);
            a1 = fma2(q1z2, zw.x, a1);
            float lo, hi;
            unpack2(a0, lo, hi);
            m00 = fminf(m00, lo); m01 = fminf(m01, hi);
            unpack2(a1, lo, hi);
            m10 = fminf(m10, lo); m11 = fminf(m11, hi);
        }
    }
    const int slot = ((chunk * 2 + dir) * 2 + b) * NPTS;
    g_minpart[slot + pt0] = fminf(m00, m01);
    g_minpart[slot + pt1] = fminf(m10, m11);
}

// ---------------------------------------------------------------------------
// Chamfer reduce: min over chunks, add |q|^2, sum.  <<<128,256>>>
// ---------------------------------------------------------------------------
__global__ __launch_bounds__(256) void chamfer_reduce_kernel(const float* __restrict__ pred,
                                                             const float* __restrict__ gt) {
    const int idx = blockIdx.x * 256 + threadIdx.x;   // 0..32767
    const int pt  = idx & (NPTS - 1);
    const int b   = (idx >> 13) & 1;
    const int dir = idx >> 14;

    const float* Q = (dir ? gt : pred) + (size_t)b * NPTS * 3 + (size_t)pt * 3;
    const float q2 = fmaf(Q[0], Q[0], fmaf(Q[1], Q[1], Q[2] * Q[2]));

    float m = INFINITY;
    #pragma unroll
    for (int c = 0; c < CHUNKS; c++)
        m = fminf(m, g_minpart[((c * 2 + dir) * 2 + b) * NPTS + pt]);

    float s = blockReduceSum(m + q2);
    if (threadIdx.x == 0) atomicAdd(&g_acc.chamfer_sum, (double)s);
}

// ---------------------------------------------------------------------------
// clDice fused, warp-per-row, barrier-free mainloop.
//   Each warp owns one (b,h) row: 128 voxels = 32 lanes x float4.
//   h-min: 3 predicated LDG.128 per array (L2-reused by neighbor warps)
//   w-min: in-register shifts + 2 shuffles per array
//   d-min: rolling float4 window registers
// sigmoid monotonic => erode raw logits, sigmoid at the end.
// grid (VH/8, VD/DCHUNK, BATCH), block 256 (8 warps)
// ---------------------------------------------------------------------------
__device__ __forceinline__ float4 f4min3(float4 a, float4 b, float4 c) {
    float4 o;
    o.x = fminf(a.x, fminf(b.x, c.x));
    o.y = fminf(a.y, fminf(b.y, c.y));
    o.z = fminf(a.z, fminf(b.z, c.z));
    o.w = fminf(a.w, fminf(b.w, c.w));
    return o;
}
__device__ __forceinline__ float4 f4min2(float4 a, float4 b) {
    float4 o;
    o.x = fminf(a.x, b.x); o.y = fminf(a.y, b.y);
    o.z = fminf(a.z, b.z); o.w = fminf(a.w, b.w);
    return o;
}
__device__ __forceinline__ float4 wmin(float4 v, int lane) {
    float l = __shfl_up_sync(0xffffffffu, v.w, 1);
    float r = __shfl_down_sync(0xffffffffu, v.x, 1);
    if (lane == 0)  l = INFINITY;
    if (lane == 31) r = INFINITY;
    float4 o;
    o.x = fminf(l,   fminf(v.x, v.y));
    o.y = fminf(v.x, fminf(v.y, v.z));
    o.z = fminf(v.y, fminf(v.z, v.w));
    o.w = fminf(v.z, fminf(v.w, r));
    return o;
}

__global__ __launch_bounds__(256) void cldice_kernel(const float* __restrict__ pv,
                                                     const float* __restrict__ gv) {
    const int lane = threadIdx.x & 31;
    const int wid  = threadIdx.x >> 5;
    const int h    = blockIdx.x * 8 + wid;
    const int d0   = blockIdx.y * DCHUNK;
    const int b    = blockIdx.z;
    const float* P = pv + (size_t)b * VOL_PER_B;
    const float* G = gv + (size_t)b * VOL_PER_B;
    const bool hm = (h > 0), hp = (h < VH - 1);
    const int col = lane * 4;

    const float4 inf4 = make_float4(INFINITY, INFINITY, INFINITY, INFINITY);
    float4 wa_p = inf4, wb_p = inf4, wa_g = inf4, wb_g = inf4;
    float accI = 0.f, accP = 0.f, accG = 0.f;

    for (int dd = d0 - 1; dd <= d0 + DCHUNK; dd++) {
        float4 ph = inf4, gh = inf4;
        if (dd >= 0 && dd < VD) {
            const size_t rb = (size_t)dd * (VH * VW) + h * VW + col;
            ph = *(const float4*)(P + rb);
            gh = *(const float4*)(G + rb);
            if (hm) {
                ph = f4min2(ph, *(const float4*)(P + rb - VW));
                gh = f4min2(gh, *(const float4*)(G + rb - VW));
            }
            if (hp) {
                ph = f4min2(ph, *(const float4*)(P + rb + VW));
                gh = f4min2(gh, *(const float4*)(G + rb + VW));
            }
        }
        const float4 pc = wmin(ph, lane);
        const float4 gc = wmin(gh, lane);
        if (dd > d0) {                       // emit dout = dd-1 in [d0, d0+DCHUNK)
            const float4 pe = f4min3(wa_p, wb_p, pc);
            const float4 ge = f4min3(wa_g, wb_g, gc);
            const float s0 = 1.f / (1.f + __expf(-pe.x));
            const float s1 = 1.f / (1.f + __expf(-pe.y));
            const float s2 = 1.f / (1.f + __expf(-pe.z));
            const float s3 = 1.f / (1.f + __expf(-pe.w));
            accI = fmaf(s0, ge.x, fmaf(s1, ge.y, fmaf(s2, ge.z, fmaf(s3, ge.w, accI))));
            accP += (s0 + s1) + (s2 + s3);
            accG += (ge.x + ge.y) + (ge.z + ge.w);
        }
        wa_p = wb_p; wb_p = pc;
        wa_g = wb_g; wb_g = gc;
    }

    float r;
    r = blockReduceSum(accI); if (threadIdx.x == 0) atomicAdd(&g_acc.inter[b], (double)r);
    r = blockReduceSum(accP); if (threadIdx.x == 0) atomicAdd(&g_acc.psum[b], (double)r);
    r = blockReduceSum(accG); if (threadIdx.x == 0) atomicAdd(&g_acc.gsum[b], (double)r);
}

// ---------------------------------------------------------------------------
// Depth loss, float4-vectorized: SILog + gradient L1 + masked L1.
// grid DPIX_TOT/1024 = 512 blocks, 256 threads, 4 px/thread (one row segment).
// ---------------------------------------------------------------------------
__global__ __launch_bounds__(256) void depth_kernel(const float* __restrict__ pred,
                                                    const float* __restrict__ gt,
                                                    const float* __restrict__ mask) {
    const int vi = blockIdx.x * 256 + threadIdx.x;    // float4 index
    const int i  = vi * 4;
    const int b  = i >> 18;                           // DPIX_PER_B = 2^18
    const int w0 = i & (DW - 1);
    const int h  = (i >> 9) & (DH - 1);

    const float4 p = ((const float4*)pred)[vi];
    const float4 g = ((const float4*)gt)[vi];
    const float4 mk = ((const float4*)mask)[vi];

    // SILog terms
    float lg0 = __logf(p.x + 0.1f) - __logf(g.x + 0.1f);
    float lg1 = __logf(p.y + 0.1f) - __logf(g.y + 0.1f);
    float lg2 = __logf(p.z + 0.1f) - __logf(g.z + 0.1f);
    float lg3 = __logf(p.w + 0.1f) - __logf(g.w + 0.1f);
    float s_g  = lg0 + lg1 + lg2 + lg3;
    float s_g2 = fmaf(lg0, lg0, fmaf(lg1, lg1, fmaf(lg2, lg2, lg3 * lg3)));

    // gradient along h (x in reference)
    float s_gx = 0.f;
    if (h < DH - 1) {
        const float4 pd = ((const float4*)pred)[vi + DW / 4];
        const float4 gd = ((const float4*)gt)[vi + DW / 4];
        s_gx += fabsf(fabsf(p.x - pd.x) - fabsf(g.x - gd.x));
        s_gx += fabsf(fabsf(p.y - pd.y) - fabsf(g.y - gd.y));
        s_gx += fabsf(fabsf(p.z - pd.z) - fabsf(g.z - gd.z));
        s_gx += fabsf(fabsf(p.w - pd.w) - fabsf(g.w - gd.w));
    }
    // gradient along w (y in reference)
    float s_gy = 0.f;
    s_gy += fabsf(fabsf(p.x - p.y) - fabsf(g.x - g.y));
    s_gy += fabsf(fabsf(p.y - p.z) - fabsf(g.y - g.z));
    s_gy += fabsf(fabsf(p.z - p.w) - fabsf(g.z - g.w));
    if (w0 + 4 < DW) {
        const float pn = pred[i + 4];
        const float gn = gt[i + 4];
        s_gy += fabsf(fabsf(p.w - pn) - fabsf(g.w - gn));
    }
    // masked L1
    float s_mn = fabsf(p.x - g.x) * mk.x + fabsf(p.y - g.y) * mk.y
               + fabsf(p.z - g.z) * mk.z + fabsf(p.w - g.w) * mk.w;
    float s_md = mk.x + mk.y + mk.z + mk.w;

    float r;
    r = blockReduceSum(s_g);  if (threadIdx.x == 0) atomicAdd(&g_acc.g_sum[b],  (double)r);
    r = blockReduceSum(s_g2); if (threadIdx.x == 0) atomicAdd(&g_acc.g2_sum[b], (double)r);
    r = blockReduceSum(s_gx); if (threadIdx.x == 0) atomicAdd(&g_acc.gradx,    (double)r);
    r = blockReduceSum(s_gy); if (threadIdx.x == 0) atomicAdd(&g_acc.grady,    (double)r);
    r = blockReduceSum(s_mn); if (threadIdx.x == 0) atomicAdd(&g_acc.mask_num, (double)r);
    r = blockReduceSum(s_md); if (threadIdx.x == 0) atomicAdd(&g_acc.mask_den, (double)r);
}

// ---------------------------------------------------------------------------
// Finalize
// ---------------------------------------------------------------------------
__global__ void finalize_kernel(const int* __restrict__ iter_ptr,
                                float* __restrict__ out) {
    if (threadIdx.x != 0 || blockIdx.x != 0) return;
    const Acc& a = g_acc;

    double chamfer = a.chamfer_sum / (double)(BATCH * NPTS);

    const double smooth = 1e-5;
    double dice0 = (2.0 * a.inter[0] + smooth) / (a.psum[0] + a.gsum[0] + smooth);
    double dice1 = (2.0 * a.inter[1] + smooth) / (a.psum[1] + a.gsum[1] + smooth);
    double cldice = 1.0 - 0.5 * (dice0 + dice1);

    const double Np = (double)DPIX_PER_B;
    double m0 = a.g_sum[0] / Np, m1 = a.g_sum[1] / Np;
    double v0 = a.g2_sum[0] / Np - m0 * m0;
    double v1 = a.g2_sum[1] / Np - m1 * m1;
    double silog = 10.0 * 0.5 * (v0 + v1) + 10.0 * 0.5 * (m0 * m0 + m1 * m1);
    double grad = a.gradx / (double)(BATCH * (DH - 1) * DW)
                + a.grady / (double)(BATCH * DH * (DW - 1));
    double mask_l1 = a.mask_num / (a.mask_den + 1e-8);
    double dloss = silog + grad + mask_l1;

    int it = *iter_ptr;
    if (it < 1) it = 1;
    double gamma1 = 2.0 * log((double)it / 20000.0);

    out[0] = (float)(gamma1 * chamfer + 0.5 * cldice + 0.01 * dloss);
}

// ---------------------------------------------------------------------------
// Launch
// ---------------------------------------------------------------------------
extern "C" void kernel_launch(void* const* d_in, const int* in_sizes, int n_in,
                              void* d_out, int out_size) {
    const float* pred_centers = (const float*)d_in[0];
    const float* pred_volume  = (const float*)d_in[1];
    const float* pred_depth   = (const float*)d_in[2];
    const float* gt_points    = (const float*)d_in[3];
    const float* gt_volume    = (const float*)d_in[4];
    const float* gt_depth     = (const float*)d_in[5];
    const float* depth_mask   = (const float*)d_in[6];
    const int*   iteration    = (const int*)d_in[7];
    float* out = (float*)d_out;

    init_kernel<<<1, 32>>>();

    dim3 cgrid(NPTS / (256 * QBLK), CHUNKS, BATCH * 2);
    chamfer_kernel<<<cgrid, 256>>>(pred_centers, gt_points);
    chamfer_reduce_kernel<<<(2 * BATCH * NPTS) / 256, 256>>>(pred_centers, gt_points);

    dim3 vgrid(VH / 8, VD / DCHUNK, BATCH);
    cldice_kernel<<<vgrid, 256>>>(pred_volume, gt_volume);

    depth_kernel<<<DPIX_TOT / 1024, 256>>>(pred_depth, gt_depth, depth_mask);

    finalize_kernel<<<1, 32>>>(iteration, out);
}

// round 4
// speedup vs baseline: 2.1054x; 1.1697x over previous
#include <cuda_runtime.h>
#include <cuda_bf16.h>
#include <math.h>

// ---------------------------------------------------------------------------
// Problem constants (fixed shapes from metadata)
// ---------------------------------------------------------------------------
#define BATCH   2
#define NPTS    8192
#define CHUNKS  32
#define CHUNK_SZ (NPTS / CHUNKS)   // 256
#define TILE    256
#define QBLK    4                  // queries per thread

#define VD 64
#define VH 128
#define VW 128
#define VOL_PER_B (VD * VH * VW)
#define DCHUNK 4

#define DH 512
#define DW 512
#define DPIX_PER_B (DH * DW)
#define DPIX_TOT   (BATCH * DPIX_PER_B)

// mega-kernel block partition
#define CH_BLOCKS 1024                 // 8 x-tiles * 32 chunks * 4 (b,dir)
#define CL_BLOCKS 512                  // 16 h-tiles * 16 d-tiles * 2 b
#define DP_BLOCKS 512                  // DPIX_TOT / 1024
#define ALL_BLOCKS (CH_BLOCKS + CL_BLOCKS + DP_BLOCKS)

// ---------------------------------------------------------------------------
// Device scratch (static — no allocations allowed)
// ---------------------------------------------------------------------------
struct Acc {
    double chamfer_sum;
    double inter[2], psum[2], gsum[2];
    double g_sum[2], g2_sum[2];
    double gradx, grady, mask_num, mask_den;
};
__device__ Acc g_acc;

__device__ float g_minpart[CHUNKS * 2 * BATCH * NPTS];   // [chunk][dir][b][pt]

// ---------------------------------------------------------------------------
// f32x2 packed helpers (sm_103a; ptxas will not auto-fuse — must be PTX)
// ---------------------------------------------------------------------------
__device__ __forceinline__ unsigned long long fma2(unsigned long long a,
                                                   unsigned long long b,
                                                   unsigned long long c) {
    unsigned long long d;
    asm("fma.rn.f32x2 %0, %1, %2, %3;" : "=l"(d) : "l"(a), "l"(b), "l"(c));
    return d;
}
__device__ __forceinline__ unsigned long long pack2(float a, float b) {
    unsigned long long r;
    asm("mov.b64 %0, {%1, %2};" : "=l"(r) : "f"(a), "f"(b));
    return r;
}
__device__ __forceinline__ void unpack2(unsigned long long v, float& a, float& b) {
    asm("mov.b64 {%0, %1}, %2;" : "=f"(a), "=f"(b) : "l"(v));
}

// ---------------------------------------------------------------------------
// Reductions
// ---------------------------------------------------------------------------
__device__ __forceinline__ float warpReduceSum(float v) {
    #pragma unroll
    for (int o = 16; o > 0; o >>= 1)
        v += __shfl_down_sync(0xffffffffu, v, o);
    return v;
}

__device__ __forceinline__ float blockReduceSum(float v) {
    __shared__ float sbuf[32];
    int lane = threadIdx.x & 31;
    int wid  = threadIdx.x >> 5;
    v = warpReduceSum(v);
    __syncthreads();
    if (lane == 0) sbuf[wid] = v;
    __syncthreads();
    if (wid == 0) {
        int nw = (blockDim.x + 31) >> 5;
        v = (lane < nw) ? sbuf[lane] : 0.f;
        v = warpReduceSum(v);
    }
    return v;
}

// ---------------------------------------------------------------------------
// Init: zero accumulators
// ---------------------------------------------------------------------------
__global__ void init_kernel() {
    double* a = (double*)&g_acc;
    const int n = sizeof(Acc) / sizeof(double);
    if (threadIdx.x < n) a[threadIdx.x] = 0.0;
}

// ---------------------------------------------------------------------------
// Helpers for cldice
// ---------------------------------------------------------------------------
__device__ __forceinline__ float4 f4min3(float4 a, float4 b, float4 c) {
    float4 o;
    o.x = fminf(a.x, fminf(b.x, c.x));
    o.y = fminf(a.y, fminf(b.y, c.y));
    o.z = fminf(a.z, fminf(b.z, c.z));
    o.w = fminf(a.w, fminf(b.w, c.w));
    return o;
}
__device__ __forceinline__ float4 f4min2(float4 a, float4 b) {
    float4 o;
    o.x = fminf(a.x, b.x); o.y = fminf(a.y, b.y);
    o.z = fminf(a.z, b.z); o.w = fminf(a.w, b.w);
    return o;
}
__device__ __forceinline__ float4 wmin(float4 v, int lane) {
    float l = __shfl_up_sync(0xffffffffu, v.w, 1);
    float r = __shfl_down_sync(0xffffffffu, v.x, 1);
    if (lane == 0)  l = INFINITY;
    if (lane == 31) r = INFINITY;
    float4 o;
    o.x = fminf(l,   fminf(v.x, v.y));
    o.y = fminf(v.x, fminf(v.y, v.z));
    o.z = fminf(v.y, fminf(v.z, v.w));
    o.w = fminf(v.z, fminf(v.w, r));
    return o;
}

// ---------------------------------------------------------------------------
// MEGA KERNEL: chamfer partials + cldice + depth, partitioned by blockIdx.x.
// All partitions use 256-thread blocks; chamfer (longest) scheduled first.
// ---------------------------------------------------------------------------
__global__ __launch_bounds__(256) void mega_kernel(
    const float* __restrict__ pred_centers, const float* __restrict__ gt_points,
    const float* __restrict__ pv, const float* __restrict__ gv,
    const float* __restrict__ pdep, const float* __restrict__ gdep,
    const float* __restrict__ mask)
{
    const int bx  = blockIdx.x;
    const int tid = threadIdx.x;

    if (bx < CH_BLOCKS) {
        // ===== Chamfer partial mins: f32x2 packed, 4 queries/thread =========
        // d'(q,g) = |g|^2 - 2 q.g ; |q|^2 added in reduce kernel.
        const int xq    = bx & 7;            // 8 x-tiles of 1024 queries
        const int chunk = (bx >> 3) & 31;    // 32 candidate chunks of 256
        const int bz    = bx >> 8;
        const int b     = bz & 1;
        const int dir   = bz >> 1;

        const float* Q = (dir ? gt_points : pred_centers) + (size_t)b * NPTS * 3;
        const float* T = (dir ? pred_centers : gt_points) + (size_t)b * NPTS * 3;

        const int pt0 = xq * (256 * QBLK) + tid;
        const int pt1 = pt0 + 256, pt2 = pt0 + 512, pt3 = pt0 + 768;

        const float q0x = Q[pt0*3+0], q0y = Q[pt0*3+1], q0z = Q[pt0*3+2];
        const float q1x = Q[pt1*3+0], q1y = Q[pt1*3+1], q1z = Q[pt1*3+2];
        const float q2x = Q[pt2*3+0], q2y = Q[pt2*3+1], q2z = Q[pt2*3+2];
        const float q3x = Q[pt3*3+0], q3y = Q[pt3*3+1], q3z = Q[pt3*3+2];
        const unsigned long long q0x2 = pack2(q0x,q0x), q0y2 = pack2(q0y,q0y), q0z2 = pack2(q0z,q0z);
        const unsigned long long q1x2 = pack2(q1x,q1x), q1y2 = pack2(q1y,q1y), q1z2 = pack2(q1z,q1z);
        const unsigned long long q2x2 = pack2(q2x,q2x), q2y2 = pack2(q2y,q2y), q2z2 = pack2(q2z,q2z);
        const unsigned long long q3x2 = pack2(q3x,q3x), q3y2 = pack2(q3y,q3y), q3z2 = pack2(q3z,q3z);

        __shared__ ulonglong2 s_xy[TILE / 2];
        __shared__ ulonglong2 s_zw[TILE / 2];

        // load one 256-candidate tile (pre-scaled by -2, |g|^2 in w)
        {
            const int j = chunk * CHUNK_SZ + tid;
            const float gx = T[j*3+0], gy = T[j*3+1], gz = T[j*3+2];
            float* fxy = (float*)s_xy;
            float* fzw = (float*)s_zw;
            const int k4 = (tid >> 1) * 4 + (tid & 1);
            fxy[k4]     = -2.f * gx;
            fxy[k4 + 2] = -2.f * gy;
            fzw[k4]     = -2.f * gz;
            fzw[k4 + 2] = fmaf(gx, gx, fmaf(gy, gy, gz * gz));
        }
        __syncthreads();

        float m0l = INFINITY, m0h = INFINITY, m1l = INFINITY, m1h = INFINITY;
        float m2l = INFINITY, m2h = INFINITY, m3l = INFINITY, m3h = INFINITY;

        #pragma unroll 4
        for (int k = 0; k < TILE / 2; k++) {
            const ulonglong2 xy = s_xy[k];
            const ulonglong2 zw = s_zw[k];
            unsigned long long a0 = fma2(q0x2, xy.x, zw.y);
            unsigned long long a1 = fma2(q1x2, xy.x, zw.y);
            unsigned long long a2 = fma2(q2x2, xy.x, zw.y);
            unsigned long long a3 = fma2(q3x2, xy.x, zw.y);
            a0 = fma2(q0y2, xy.y, a0);
            a1 = fma2(q1y2, xy.y, a1);
            a2 = fma2(q2y2, xy.y, a2);
            a3 = fma2(q3y2, xy.y, a3);
            a0 = fma2(q0z2, zw.x, a0);
            a1 = fma2(q1z2, zw.x, a1);
            a2 = fma2(q2z2, zw.x, a2);
            a3 = fma2(q3z2, zw.x, a3);
            float lo, hi;
            unpack2(a0, lo, hi); m0l = fminf(m0l, lo); m0h = fminf(m0h, hi);
            unpack2(a1, lo, hi); m1l = fminf(m1l, lo); m1h = fminf(m1h, hi);
            unpack2(a2, lo, hi); m2l = fminf(m2l, lo); m2h = fminf(m2h, hi);
            unpack2(a3, lo, hi); m3l = fminf(m3l, lo); m3h = fminf(m3h, hi);
        }
        const int slot = ((chunk * 2 + dir) * 2 + b) * NPTS;
        g_minpart[slot + pt0] = fminf(m0l, m0h);
        g_minpart[slot + pt1] = fminf(m1l, m1h);
        g_minpart[slot + pt2] = fminf(m2l, m2h);
        g_minpart[slot + pt3] = fminf(m3l, m3h);

    } else if (bx < CH_BLOCKS + CL_BLOCKS) {
        // ===== clDice: fused separable 3x3x3 min-pool + sigmoid + reduce ====
        const int bi   = bx - CH_BLOCKS;
        const int lane = tid & 31;
        const int wid  = tid >> 5;
        const int h    = (bi & 15) * 8 + wid;
        const int d0   = ((bi >> 4) & 15) * DCHUNK;
        const int b    = bi >> 8;
        const float* P = pv + (size_t)b * VOL_PER_B;
        const float* G = gv + (size_t)b * VOL_PER_B;
        const bool hm = (h > 0), hp = (h < VH - 1);
        const int col = lane * 4;

        const float4 inf4 = make_float4(INFINITY, INFINITY, INFINITY, INFINITY);
        float4 wa_p = inf4, wb_p = inf4, wa_g = inf4, wb_g = inf4;
        float accI = 0.f, accP = 0.f, accG = 0.f;

        for (int dd = d0 - 1; dd <= d0 + DCHUNK; dd++) {
            float4 ph = inf4, gh = inf4;
            if (dd >= 0 && dd < VD) {
                const size_t rb = (size_t)dd * (VH * VW) + h * VW + col;
                ph = *(const float4*)(P + rb);
                gh = *(const float4*)(G + rb);
                if (hm) {
                    ph = f4min2(ph, *(const float4*)(P + rb - VW));
                    gh = f4min2(gh, *(const float4*)(G + rb - VW));
                }
                if (hp) {
                    ph = f4min2(ph, *(const float4*)(P + rb + VW));
                    gh = f4min2(gh, *(const float4*)(G + rb + VW));
                }
            }
            const float4 pc = wmin(ph, lane);
            const float4 gc = wmin(gh, lane);
            if (dd > d0) {
                const float4 pe = f4min3(wa_p, wb_p, pc);
                const float4 ge = f4min3(wa_g, wb_g, gc);
                const float s0 = 1.f / (1.f + __expf(-pe.x));
                const float s1 = 1.f / (1.f + __expf(-pe.y));
                const float s2 = 1.f / (1.f + __expf(-pe.z));
                const float s3 = 1.f / (1.f + __expf(-pe.w));
                accI = fmaf(s0, ge.x, fmaf(s1, ge.y, fmaf(s2, ge.z, fmaf(s3, ge.w, accI))));
                accP += (s0 + s1) + (s2 + s3);
                accG += (ge.x + ge.y) + (ge.z + ge.w);
            }
            wa_p = wb_p; wb_p = pc;
            wa_g = wb_g; wb_g = gc;
        }

        float r;
        r = blockReduceSum(accI); if (tid == 0) atomicAdd(&g_acc.inter[b], (double)r);
        r = blockReduceSum(accP); if (tid == 0) atomicAdd(&g_acc.psum[b], (double)r);
        r = blockReduceSum(accG); if (tid == 0) atomicAdd(&g_acc.gsum[b], (double)r);

    } else {
        // ===== Depth loss: SILog + gradient L1 + masked L1, float4 ==========
        const int bi = bx - CH_BLOCKS - CL_BLOCKS;
        const int vi = bi * 256 + tid;
        const int i  = vi * 4;
        const int b  = i >> 18;
        const int w0 = i & (DW - 1);
        const int h  = (i >> 9) & (DH - 1);

        const float4 p  = ((const float4*)pdep)[vi];
        const float4 g  = ((const float4*)gdep)[vi];
        const float4 mk = ((const float4*)mask)[vi];

        float lg0 = __logf(p.x + 0.1f) - __logf(g.x + 0.1f);
        float lg1 = __logf(p.y + 0.1f) - __logf(g.y + 0.1f);
        float lg2 = __logf(p.z + 0.1f) - __logf(g.z + 0.1f);
        float lg3 = __logf(p.w + 0.1f) - __logf(g.w + 0.1f);
        float s_g  = lg0 + lg1 + lg2 + lg3;
        float s_g2 = fmaf(lg0, lg0, fmaf(lg1, lg1, fmaf(lg2, lg2, lg3 * lg3)));

        float s_gx = 0.f;
        if (h < DH - 1) {
            const float4 pd = ((const float4*)pdep)[vi + DW / 4];
            const float4 gd = ((const float4*)gdep)[vi + DW / 4];
            s_gx += fabsf(fabsf(p.x - pd.x) - fabsf(g.x - gd.x));
            s_gx += fabsf(fabsf(p.y - pd.y) - fabsf(g.y - gd.y));
            s_gx += fabsf(fabsf(p.z - pd.z) - fabsf(g.z - gd.z));
            s_gx += fabsf(fabsf(p.w - pd.w) - fabsf(g.w - gd.w));
        }
        float s_gy = 0.f;
        s_gy += fabsf(fabsf(p.x - p.y) - fabsf(g.x - g.y));
        s_gy += fabsf(fabsf(p.y - p.z) - fabsf(g.y - g.z));
        s_gy += fabsf(fabsf(p.z - p.w) - fabsf(g.z - g.w));
        if (w0 + 4 < DW) {
            const float pn = pdep[i + 4];
            const float gn = gdep[i + 4];
            s_gy += fabsf(fabsf(p.w - pn) - fabsf(g.w - gn));
        }
        float s_mn = fabsf(p.x - g.x) * mk.x + fabsf(p.y - g.y) * mk.y
                   + fabsf(p.z - g.z) * mk.z + fabsf(p.w - g.w) * mk.w;
        float s_md = mk.x + mk.y + mk.z + mk.w;

        float r;
        r = blockReduceSum(s_g);  if (tid == 0) atomicAdd(&g_acc.g_sum[b],  (double)r);
        r = blockReduceSum(s_g2); if (tid == 0) atomicAdd(&g_acc.g2_sum[b], (double)r);
        r = blockReduceSum(s_gx); if (tid == 0) atomicAdd(&g_acc.gradx,    (double)r);
        r = blockReduceSum(s_gy); if (tid == 0) atomicAdd(&g_acc.grady,    (double)r);
        r = blockReduceSum(s_mn); if (tid == 0) atomicAdd(&g_acc.mask_num, (double)r);
        r = blockReduceSum(s_md); if (tid == 0) atomicAdd(&g_acc.mask_den, (double)r);
    }
}

// ---------------------------------------------------------------------------
// Chamfer reduce: min over chunks, add |q|^2, sum.  <<<128,256>>>
// ---------------------------------------------------------------------------
__global__ __launch_bounds__(256) void chamfer_reduce_kernel(const float* __restrict__ pred,
                                                             const float* __restrict__ gt) {
    const int idx = blockIdx.x * 256 + threadIdx.x;   // 0..32767
    const int pt  = idx & (NPTS - 1);
    const int b   = (idx >> 13) & 1;
    const int dir = idx >> 14;

    const float* Q = (dir ? gt : pred) + (size_t)b * NPTS * 3 + (size_t)pt * 3;
    const float q2 = fmaf(Q[0], Q[0], fmaf(Q[1], Q[1], Q[2] * Q[2]));

    float m = INFINITY;
    #pragma unroll
    for (int c = 0; c < CHUNKS; c++)
        m = fminf(m, g_minpart[((c * 2 + dir) * 2 + b) * NPTS + pt]);

    float s = blockReduceSum(m + q2);
    if (threadIdx.x == 0) atomicAdd(&g_acc.chamfer_sum, (double)s);
}

// ---------------------------------------------------------------------------
// Finalize
// ---------------------------------------------------------------------------
__global__ void finalize_kernel(const int* __restrict__ iter_ptr,
                                float* __restrict__ out) {
    if (threadIdx.x != 0 || blockIdx.x != 0) return;
    const Acc& a = g_acc;

    double chamfer = a.chamfer_sum / (double)(BATCH * NPTS);

    const double smooth = 1e-5;
    double dice0 = (2.0 * a.inter[0] + smooth) / (a.psum[0] + a.gsum[0] + smooth);
    double dice1 = (2.0 * a.inter[1] + smooth) / (a.psum[1] + a.gsum[1] + smooth);
    double cldice = 1.0 - 0.5 * (dice0 + dice1);

    const double Np = (double)DPIX_PER_B;
    double m0 = a.g_sum[0] / Np, m1 = a.g_sum[1] / Np;
    double v0 = a.g2_sum[0] / Np - m0 * m0;
    double v1 = a.g2_sum[1] / Np - m1 * m1;
    double silog = 10.0 * 0.5 * (v0 + v1) + 10.0 * 0.5 * (m0 * m0 + m1 * m1);
    double grad = a.gradx / (double)(BATCH * (DH - 1) * DW)
                + a.grady / (double)(BATCH * DH * (DW - 1));
    double mask_l1 = a.mask_num / (a.mask_den + 1e-8);
    double dloss = silog + grad + mask_l1;

    int it = *iter_ptr;
    if (it < 1) it = 1;
    double gamma1 = 2.0 * log((double)it / 20000.0);

    out[0] = (float)(gamma1 * chamfer + 0.5 * cldice + 0.01 * dloss);
}

// ---------------------------------------------------------------------------
// Launch
// ---------------------------------------------------------------------------
extern "C" void kernel_launch(void* const* d_in, const int* in_sizes, int n_in,
                              void* d_out, int out_size) {
    const float* pred_centers = (const float*)d_in[0];
    const float* pred_volume  = (const float*)d_in[1];
    const float* pred_depth   = (const float*)d_in[2];
    const float* gt_points    = (const float*)d_in[3];
    const float* gt_volume    = (const float*)d_in[4];
    const float* gt_depth     = (const float*)d_in[5];
    const float* depth_mask   = (const float*)d_in[6];
    const int*   iteration    = (const int*)d_in[7];
    float* out = (float*)d_out;

    init_kernel<<<1, 32>>>();

    mega_kernel<<<ALL_BLOCKS, 256>>>(pred_centers, gt_points,
                                     pred_volume, gt_volume,
                                     pred_depth, gt_depth, depth_mask);

    chamfer_reduce_kernel<<<(2 * BATCH * NPTS) / 256, 256>>>(pred_centers, gt_points);

    finalize_kernel<<<1, 32>>>(iteration, out);
}